// round 1
// baseline (speedup 1.0000x reference)
#include <cuda_runtime.h>
#include <math.h>

#define EE 64
#define SSZ 128
#define FF 640
#define HH 256
#define GG 768          // 3*H
#define LLN 20
#define CC 32
#define BB (EE*SSZ)     // 8192
#define BLM (BB*LLN)    // 163840
#define EPSV 1e-5f

// ---------------- scratch (static __device__, no allocation) ----------------
__device__ float g_x [BB*HH];       // 8 MB
__device__ float g_gi[BB*GG];       // 24 MB
__device__ float g_h [BB*HH];       // 8 MB
__device__ float g_gh[BB*GG];       // 24 MB
__device__ float g_hs[BLM*HH];      // 160 MB, layout [b][l][h]
__device__ float g_y2[BLM*HH];      // 160 MB
__device__ float g_s1[HH], g_o1[HH];
__device__ float g_s2[HH], g_o2[HH];
__device__ float g_s3[HH], g_o3[HH];
__device__ float g_al[3];

// ---------------- prep: fold BN params into scale/offset --------------------
__global__ void prep_kernel(const float* g1,const float* b1,const float* m1,const float* v1,const float* a1,
                            const float* g2,const float* b2,const float* m2,const float* v2,const float* a2,
                            const float* g3,const float* b3,const float* m3,const float* v3,const float* a3)
{
    int i = threadIdx.x;   // 256 threads, H=256
    float s;
    s = g1[i] / sqrtf(v1[i] + EPSV); g_s1[i] = s; g_o1[i] = b1[i] - m1[i]*s;
    s = g2[i] / sqrtf(v2[i] + EPSV); g_s2[i] = s; g_o2[i] = b2[i] - m2[i]*s;
    s = g3[i] / sqrtf(v3[i] + EPSV); g_s3[i] = s; g_o3[i] = b3[i] - m3[i]*s;
    if (i == 0) { g_al[0] = a1[0]; g_al[1] = a2[0]; g_al[2] = a3[0]; }
}

__global__ void zero_h_kernel()
{
    int i = blockIdx.x * blockDim.x + threadIdx.x;   // over BB*HH/4
    ((float4*)g_h)[i] = make_float4(0.f, 0.f, 0.f, 0.f);
}

// ---------------- generic tiled fp32 GEMM:  C = epi(A @ W^T + bias) ---------
// A:[M,K] row-major, W:[N,K] row-major.
// MODE 0: bias only
// MODE 1: bias, then BN1+PReLU epilogue (g_s1/g_o1/g_al[0])
// MODE 2: A-load transform BN2+PReLU (g_s2/g_o2/g_al[1]);
//         epilogue bias + BN3+PReLU (g_s3/g_o3/g_al[2])
template<int BM,int BN,int BK,int TM,int TN,int MODE>
__global__ __launch_bounds__(256, 2) void gemm_kernel(
    const float* __restrict__ A, const float* __restrict__ W,
    const float* __restrict__ bias, float* __restrict__ Cst,
    int M, int N, int K)
{
    __shared__ float As[BK][BM];
    __shared__ float Ws[BK][BN];

    const int tid = threadIdx.x;
    const int m0  = blockIdx.y * BM;
    const int n0  = blockIdx.x * BN;
    constexpr int CT = BN / TN;          // threads along N (16)
    const int tr = tid / CT;             // 0..15
    const int tc = tid % CT;             // 0..15
    constexpr int TNh = TN / 2;

    float aA = 0.f;
    if (MODE == 2) aA = g_al[1];

    float acc[TM][TN];
#pragma unroll
    for (int i = 0; i < TM; i++)
#pragma unroll
        for (int j = 0; j < TN; j++) acc[i][j] = 0.f;

    constexpr int NF4A = BM*BK/4;
    constexpr int NF4W = BN*BK/4;
    constexpr int KF4  = BK/4;

    for (int k0 = 0; k0 < K; k0 += BK) {
        // ---- load A tile (coalesced float4 along K, store transposed) ----
#pragma unroll
        for (int it = 0; it < (NF4A + 255) / 256; it++) {
            int idx = tid + it * 256;
            if ((NF4A % 256 == 0) || idx < NF4A) {
                int r = idx / KF4, c = idx % KF4;
                float4 v = *(const float4*)(A + (size_t)(m0 + r) * K + k0 + c*4);
                if (MODE == 2) {
                    float4 s2 = *(const float4*)(g_s2 + k0 + c*4);
                    float4 o2 = *(const float4*)(g_o2 + k0 + c*4);
                    v.x = v.x*s2.x + o2.x; v.x = v.x >= 0.f ? v.x : aA*v.x;
                    v.y = v.y*s2.y + o2.y; v.y = v.y >= 0.f ? v.y : aA*v.y;
                    v.z = v.z*s2.z + o2.z; v.z = v.z >= 0.f ? v.z : aA*v.z;
                    v.w = v.w*s2.w + o2.w; v.w = v.w >= 0.f ? v.w : aA*v.w;
                }
                As[c*4+0][r] = v.x; As[c*4+1][r] = v.y;
                As[c*4+2][r] = v.z; As[c*4+3][r] = v.w;
            }
        }
        // ---- load W tile ----
#pragma unroll
        for (int it = 0; it < (NF4W + 255) / 256; it++) {
            int idx = tid + it * 256;
            if ((NF4W % 256 == 0) || idx < NF4W) {
                int r = idx / KF4, c = idx % KF4;
                float4 v = *(const float4*)(W + (size_t)(n0 + r) * K + k0 + c*4);
                Ws[c*4+0][r] = v.x; Ws[c*4+1][r] = v.y;
                Ws[c*4+2][r] = v.z; Ws[c*4+3][r] = v.w;
            }
        }
        __syncthreads();

#pragma unroll
        for (int k = 0; k < BK; k++) {
            float ra[TM], rb[TN];
            // A rows: contiguous tr*TM..  (broadcast across warp -> conflict free)
            float4 a0 = *(const float4*)&As[k][tr*TM];
            float4 a1 = *(const float4*)&As[k][tr*TM + 4];
            ra[0]=a0.x; ra[1]=a0.y; ra[2]=a0.z; ra[3]=a0.w;
            ra[4]=a1.x; ra[5]=a1.y; ra[6]=a1.z; ra[7]=a1.w;
            // B cols: split halves (tc*TNh and BN/2+tc*TNh) -> bank-conflict free
            if constexpr (TN == 8) {
                float4 b0 = *(const float4*)&Ws[k][tc*4];
                float4 b1 = *(const float4*)&Ws[k][BN/2 + tc*4];
                rb[0]=b0.x; rb[1]=b0.y; rb[2]=b0.z; rb[3]=b0.w;
                rb[4]=b1.x; rb[5]=b1.y; rb[6]=b1.z; rb[7]=b1.w;
            } else {   // TN == 2
                rb[0] = Ws[k][tc];
                rb[1] = Ws[k][BN/2 + tc];
            }
#pragma unroll
            for (int i = 0; i < TM; i++)
#pragma unroll
                for (int j = 0; j < TN; j++)
                    acc[i][j] = fmaf(ra[i], rb[j], acc[i][j]);
        }
        __syncthreads();
    }

    // ---- epilogue ----
#pragma unroll
    for (int j = 0; j < TN; j++) {
        int n = n0 + ((j < TNh) ? (tc*TNh + j) : (BN/2 + tc*TNh + (j - TNh)));
        float bsv = bias[n];
        float sc = 1.f, off = 0.f, al = 0.f;
        if (MODE == 1) { sc = g_s1[n]; off = g_o1[n]; al = g_al[0]; }
        if (MODE == 2) { sc = g_s3[n]; off = g_o3[n]; al = g_al[2]; }
#pragma unroll
        for (int i = 0; i < TM; i++) {
            int m = m0 + tr*TM + i;
            float v = acc[i][j] + bsv;
            if (MODE >= 1) { v = v*sc + off; v = v >= 0.f ? v : al*v; }
            Cst[(size_t)m * N + n] = v;
        }
    }
}

// ---------------- GRU gate elementwise step ---------------------------------
__device__ __forceinline__ float sigf(float x) { return 1.f / (1.f + expf(-x)); }

__global__ void gate_kernel(int l)
{
    int idx = blockIdx.x * blockDim.x + threadIdx.x;   // over BB*HH/4
    int j4 = idx % (HH/4);
    int b  = idx / (HH/4);
    int base = b * (GG/4);

    float4 gir = ((const float4*)g_gi)[base            + j4];
    float4 giz = ((const float4*)g_gi)[base +   HH/4   + j4];
    float4 gin = ((const float4*)g_gi)[base + 2*(HH/4) + j4];
    float4 ghr = ((const float4*)g_gh)[base            + j4];
    float4 ghz = ((const float4*)g_gh)[base +   HH/4   + j4];
    float4 ghn = ((const float4*)g_gh)[base + 2*(HH/4) + j4];
    float4 h   = ((const float4*)g_h )[b*(HH/4) + j4];

    float r, z, n;
    r = sigf(gir.x + ghr.x); z = sigf(giz.x + ghz.x);
    n = tanhf(gin.x + r*ghn.x); h.x = (1.f - z)*n + z*h.x;
    r = sigf(gir.y + ghr.y); z = sigf(giz.y + ghz.y);
    n = tanhf(gin.y + r*ghn.y); h.y = (1.f - z)*n + z*h.y;
    r = sigf(gir.z + ghr.z); z = sigf(giz.z + ghz.z);
    n = tanhf(gin.z + r*ghn.z); h.z = (1.f - z)*n + z*h.z;
    r = sigf(gir.w + ghr.w); z = sigf(giz.w + ghz.w);
    n = tanhf(gin.w + r*ghn.w); h.w = (1.f - z)*n + z*h.w;

    ((float4*)g_h)[b*(HH/4) + j4] = h;
    ((float4*)g_hs)[((size_t)b*LLN + l)*(HH/4) + j4] = h;
}

// ---------------- launch ----------------------------------------------------
extern "C" void kernel_launch(void* const* d_in, const int* in_sizes, int n_in,
                              void* d_out, int out_size)
{
    const float* A     = (const float*)d_in[0];   // [E,S,F] -> [8192,640]
    const float* W_lin = (const float*)d_in[1];
    const float* b_lin = (const float*)d_in[2];
    const float* g1    = (const float*)d_in[3];
    const float* be1   = (const float*)d_in[4];
    const float* m1    = (const float*)d_in[5];
    const float* v1    = (const float*)d_in[6];
    const float* a1    = (const float*)d_in[7];
    const float* W_ih  = (const float*)d_in[8];
    const float* W_hh  = (const float*)d_in[9];
    const float* b_ih  = (const float*)d_in[10];
    const float* b_hh  = (const float*)d_in[11];
    const float* g2    = (const float*)d_in[12];
    const float* be2   = (const float*)d_in[13];
    const float* m2    = (const float*)d_in[14];
    const float* v2    = (const float*)d_in[15];
    const float* a2    = (const float*)d_in[16];
    const float* Wc    = (const float*)d_in[17];
    const float* bc    = (const float*)d_in[18];
    const float* g3    = (const float*)d_in[19];
    const float* be3   = (const float*)d_in[20];
    const float* m3    = (const float*)d_in[21];
    const float* v3    = (const float*)d_in[22];
    const float* a3    = (const float*)d_in[23];
    const float* W_mu  = (const float*)d_in[24];
    const float* b_mu  = (const float*)d_in[25];
    float* out = (float*)d_out;

    float *px, *pgi, *ph, *pgh, *phs, *py2;
    cudaGetSymbolAddress((void**)&px,  g_x);
    cudaGetSymbolAddress((void**)&pgi, g_gi);
    cudaGetSymbolAddress((void**)&ph,  g_h);
    cudaGetSymbolAddress((void**)&pgh, g_gh);
    cudaGetSymbolAddress((void**)&phs, g_hs);
    cudaGetSymbolAddress((void**)&py2, g_y2);

    prep_kernel<<<1, 256>>>(g1, be1, m1, v1, a1, g2, be2, m2, v2, a2, g3, be3, m3, v3, a3);
    zero_h_kernel<<<(BB*HH/4)/256, 256>>>();

    // x = PReLU(BN1(A @ W_lin^T + b_lin))  : [8192,256], K=640
    gemm_kernel<128,128,16,8,8,1><<<dim3(HH/128, BB/128), 256>>>(A, W_lin, b_lin, px, BB, HH, FF);

    // gi = x @ W_ih^T + b_ih : [8192,768], K=256
    gemm_kernel<128,128,16,8,8,0><<<dim3(GG/128, BB/128), 256>>>(px, W_ih, b_ih, pgi, BB, GG, HH);

    // GRU recurrence
    for (int l = 0; l < LLN; l++) {
        gemm_kernel<128,128,16,8,8,0><<<dim3(GG/128, BB/128), 256>>>(ph, W_hh, b_hh, pgh, BB, GG, HH);
        gate_kernel<<<(BB*HH/4)/256, 256>>>(l);
    }

    // y2 = PReLU(BN3(PReLU(BN2(hs)) @ Wc^T + bc)) : [163840,256], K=256
    gemm_kernel<128,128,16,8,8,2><<<dim3(HH/128, BLM/128), 256>>>(phs, Wc, bc, py2, BLM, HH, HH);

    // pred = y2 @ W_mu^T + b_mu : [163840,32] -> matches (E,S,L,C) layout
    gemm_kernel<128,32,16,8,2,0><<<dim3(1, BLM/128), 256>>>(py2, W_mu, b_mu, out, BLM, CC, HH);
}